// round 2
// baseline (speedup 1.0000x reference)
#include <cuda_runtime.h>
#include <math.h>

#define NNODES 50000
#define EEDGES 800000
#define ETOT   (EEDGES + NNODES)
#define DHID   128
#define DFEAT  256          // HEADS * HID
#define NEG_SLOPE 0.2f
#define EPSV 1e-16f

// ---------------- scratch (no allocation allowed) ----------------
__device__ float g_h1[NNODES * DFEAT];
__device__ float g_agg1[NNODES * DFEAT];
__device__ float g_h2[NNODES * DFEAT];
__device__ float g_agg2[NNODES * DFEAT];
__device__ float g_as[NNODES * 2];
__device__ float g_ad[NNODES * 2];
__device__ float g_w[ETOT * 2];
__device__ float g_den[NNODES * 2];
__device__ float g_wc[DFEAT + 1];

// ---------------- zero ----------------
__global__ void zero_kernel(float4* p, int n4) {
    int i = blockIdx.x * blockDim.x + threadIdx.x;
    if (i < n4) p[i] = make_float4(0.f, 0.f, 0.f, 0.f);
}

// ---------------- tiled fp32 GEMM: C[M,N] = op(A)[M,K] @ B[K,N] ----------------
// op(A) = relu(A + bias[k]) if FUSE_RELU, else A.  BM=128, BN=64, BK=16, 256 thr.
template <int FUSE_RELU>
__global__ void __launch_bounds__(256) gemm_kernel(
    const float* __restrict__ A, const float* __restrict__ B,
    const float* __restrict__ bias, float* __restrict__ C,
    int M, int N, int K)
{
    __shared__ float As[16][132];   // transposed: As[k][m], padded
    __shared__ float Bs[16][64];

    const int m0 = blockIdx.x * 128;
    const int n0 = blockIdx.y * 64;
    const int tid = threadIdx.x;
    const int tx = tid & 15;        // output col group (4 cols)
    const int ty = tid >> 4;        // output row group (8 rows)

    float acc[8][4];
#pragma unroll
    for (int i = 0; i < 8; i++)
#pragma unroll
        for (int j = 0; j < 4; j++) acc[i][j] = 0.f;

    for (int k0 = 0; k0 < K; k0 += 16) {
        // load A tile: 128x16 = 512 float4, 2 per thread
#pragma unroll
        for (int l = 0; l < 2; l++) {
            int idx = tid + l * 256;
            int row = idx >> 2;          // 0..127
            int cg  = idx & 3;           // 0..3
            int gm = m0 + row;
            float4 f = make_float4(0.f, 0.f, 0.f, 0.f);
            if (gm < M)
                f = *(const float4*)&A[(size_t)gm * K + k0 + cg * 4];
            if (FUSE_RELU) {
                float4 bb = *(const float4*)&bias[k0 + cg * 4];
                f.x = fmaxf(f.x + bb.x, 0.f);
                f.y = fmaxf(f.y + bb.y, 0.f);
                f.z = fmaxf(f.z + bb.z, 0.f);
                f.w = fmaxf(f.w + bb.w, 0.f);
            }
            As[cg * 4 + 0][row] = f.x;
            As[cg * 4 + 1][row] = f.y;
            As[cg * 4 + 2][row] = f.z;
            As[cg * 4 + 3][row] = f.w;
        }
        // load B tile: 16x64 = 256 float4, 1 per thread
        {
            int row = tid >> 4;          // 0..15
            int cg  = tid & 15;          // 0..15
            float4 f = *(const float4*)&B[(size_t)(k0 + row) * N + n0 + cg * 4];
            *(float4*)&Bs[row][cg * 4] = f;
        }
        __syncthreads();

#pragma unroll
        for (int k = 0; k < 16; k++) {
            float br[4];
            float4 b4 = *(const float4*)&Bs[k][tx * 4];
            br[0] = b4.x; br[1] = b4.y; br[2] = b4.z; br[3] = b4.w;
            float ar[8];
#pragma unroll
            for (int i = 0; i < 8; i++) ar[i] = As[k][ty * 8 + i];
#pragma unroll
            for (int i = 0; i < 8; i++)
#pragma unroll
                for (int j = 0; j < 4; j++)
                    acc[i][j] = fmaf(ar[i], br[j], acc[i][j]);
        }
        __syncthreads();
    }

#pragma unroll
    for (int i = 0; i < 8; i++) {
        int gm = m0 + ty * 8 + i;
        if (gm < M) {
            float4 o = make_float4(acc[i][0], acc[i][1], acc[i][2], acc[i][3]);
            *(float4*)&C[(size_t)gm * N + n0 + tx * 4] = o;
        }
    }
}

// ---------------- per-(node,head) attention logits ----------------
__global__ void alpha_kernel(const float* __restrict__ h,
                             const float* __restrict__ a_src,
                             const float* __restrict__ a_dst,
                             float* __restrict__ as_out, float* __restrict__ ad_out,
                             int N)
{
    int gw = (blockIdx.x * blockDim.x + threadIdx.x) >> 5;
    int lane = threadIdx.x & 31;
    if (gw >= N * 2) return;
    int n = gw >> 1, hh = gw & 1;
    const float* hp = h + (size_t)n * DFEAT + hh * DHID;
    float4 v = *(const float4*)&hp[lane * 4];
    float4 s = *(const float4*)&a_src[hh * DHID + lane * 4];
    float4 d = *(const float4*)&a_dst[hh * DHID + lane * 4];
    float accs = v.x * s.x + v.y * s.y + v.z * s.z + v.w * s.w;
    float accd = v.x * d.x + v.y * d.y + v.z * d.z + v.w * d.w;
#pragma unroll
    for (int o = 16; o; o >>= 1) {
        accs += __shfl_xor_sync(0xffffffffu, accs, o);
        accd += __shfl_xor_sync(0xffffffffu, accd, o);
    }
    if (lane == 0) { as_out[gw] = accs; ad_out[gw] = accd; }
}

// ---------------- edge pass 1: w = exp(leakyrelu(e)); denom += w ----------------
// No max-subtraction: logits have sigma~1.3 so exp is safe; identical math.
__global__ void edge_w_kernel(const int* __restrict__ ei,
                              const float* __restrict__ as_in,
                              const float* __restrict__ ad_in,
                              float* __restrict__ wbuf, float* __restrict__ den,
                              int E, int Etot)
{
    int t = blockIdx.x * blockDim.x + threadIdx.x;
    if (t >= Etot * 2) return;
    int e = t >> 1, hh = t & 1;
    int s, d;
    if (e < E) { s = ei[e]; d = ei[E + e]; } else { s = d = e - E; }
    float ev = as_in[s * 2 + hh] + ad_in[d * 2 + hh];
    ev = ev > 0.f ? ev : NEG_SLOPE * ev;
    float wv = expf(ev);
    wbuf[t] = wv;
    atomicAdd(&den[d * 2 + hh], wv);
}

// ---------------- edge pass 2: out[dst] += alpha * h[src] ----------------
__global__ void edge_agg_kernel(const int* __restrict__ ei,
                                const float* __restrict__ h,
                                const float* __restrict__ wbuf,
                                const float* __restrict__ den,
                                float* __restrict__ out,
                                int E, int Etot)
{
    int gw = (blockIdx.x * blockDim.x + threadIdx.x) >> 5;
    int lane = threadIdx.x & 31;
    if (gw >= Etot * 2) return;
    int e = gw >> 1, hh = gw & 1;
    int s, d;
    if (e < E) { s = ei[e]; d = ei[E + e]; } else { s = d = e - E; }
    float alpha = wbuf[gw] / (den[d * 2 + hh] + EPSV);
    const float* hp = h + (size_t)s * DFEAT + hh * DHID + lane * 4;
    float* op = out + (size_t)d * DFEAT + hh * DHID + lane * 4;
    float4 v = *(const float4*)hp;
    atomicAdd(op + 0, v.x * alpha);
    atomicAdd(op + 1, v.y * alpha);
    atomicAdd(op + 2, v.z * alpha);
    atomicAdd(op + 3, v.w * alpha);
}

// ---------------- collapse post-MLP: Wc = Wp1 @ Wp2, bc = bp1@Wp2 + bp2 ----------------
__global__ void wc_kernel(const float* __restrict__ Wp1, const float* __restrict__ bp1,
                          const float* __restrict__ Wp2, const float* __restrict__ bp2,
                          float* __restrict__ wc)
{
    int i = threadIdx.x;  // 256 threads
    float acc = 0.f;
    for (int j = 0; j < DHID; j++) acc += Wp1[i * DHID + j] * Wp2[j];
    wc[i] = acc;
    if (i == 0) {
        float b = 0.f;
        for (int j = 0; j < DHID; j++) b += bp1[j] * Wp2[j];
        wc[DFEAT] = b + bp2[0];
    }
}

// ---------------- final: out[n] = sigmoid(dot(relu(agg2+b2), Wc) + bc) ----------------
__global__ void final_kernel(const float* __restrict__ agg2,
                             const float* __restrict__ b2,
                             const float* __restrict__ wc,
                             float* __restrict__ out, int N)
{
    int gw = (blockIdx.x * blockDim.x + threadIdx.x) >> 5;
    int lane = threadIdx.x & 31;
    if (gw >= N) return;
    const float* hp = agg2 + (size_t)gw * DFEAT;
    float acc = 0.f;
#pragma unroll
    for (int r = 0; r < 2; r++) {
        int c = r * 128 + lane * 4;
        float4 v  = *(const float4*)&hp[c];
        float4 bb = *(const float4*)&b2[c];
        float4 ww = *(const float4*)&wc[c];
        acc += fmaxf(v.x + bb.x, 0.f) * ww.x;
        acc += fmaxf(v.y + bb.y, 0.f) * ww.y;
        acc += fmaxf(v.z + bb.z, 0.f) * ww.z;
        acc += fmaxf(v.w + bb.w, 0.f) * ww.w;
    }
#pragma unroll
    for (int o = 16; o; o >>= 1) acc += __shfl_xor_sync(0xffffffffu, acc, o);
    if (lane == 0) {
        float z = acc + wc[DFEAT];
        out[gw] = 1.f / (1.f + expf(-z));
    }
}

// ---------------- launch ----------------
extern "C" void kernel_launch(void* const* d_in, const int* in_sizes, int n_in,
                              void* d_out, int out_size)
{
    const float* x      = (const float*)d_in[0];
    const int*   ei     = (const int*)  d_in[1];
    const float* W1     = (const float*)d_in[2];
    const float* a_src1 = (const float*)d_in[3];
    const float* a_dst1 = (const float*)d_in[4];
    const float* b1     = (const float*)d_in[5];
    const float* W2     = (const float*)d_in[6];
    const float* a_src2 = (const float*)d_in[7];
    const float* a_dst2 = (const float*)d_in[8];
    const float* b2     = (const float*)d_in[9];
    const float* Wp1    = (const float*)d_in[10];
    const float* bp1    = (const float*)d_in[11];
    const float* Wp2    = (const float*)d_in[12];
    const float* bp2    = (const float*)d_in[13];

    const int N = in_sizes[0] / 128;
    const int E = in_sizes[1] / 2;
    const int Etot = E + N;

    float *h1, *agg1, *h2, *agg2, *as, *ad, *wb, *den, *wc;
    cudaGetSymbolAddress((void**)&h1,  g_h1);
    cudaGetSymbolAddress((void**)&agg1, g_agg1);
    cudaGetSymbolAddress((void**)&h2,  g_h2);
    cudaGetSymbolAddress((void**)&agg2, g_agg2);
    cudaGetSymbolAddress((void**)&as,  g_as);
    cudaGetSymbolAddress((void**)&ad,  g_ad);
    cudaGetSymbolAddress((void**)&wb,  g_w);
    cudaGetSymbolAddress((void**)&den, g_den);
    cudaGetSymbolAddress((void**)&wc,  g_wc);

    const int featN4 = N * DFEAT / 4;
    const int denN4  = N * 2 / 4;
    dim3 gemm_grid((N + 127) / 128, DFEAT / 64);
    const int alpha_blocks = (N * 2 * 32 + 255) / 256;
    const int edgew_blocks = (Etot * 2 + 255) / 256;
    const int agg_blocks   = ((size_t)Etot * 2 * 32 + 255) / 256;
    const int final_blocks = (N * 32 + 255) / 256;

    // ---- layer 1 ----
    zero_kernel<<<(featN4 + 255) / 256, 256>>>((float4*)agg1, featN4);
    zero_kernel<<<(denN4 + 255) / 256, 256>>>((float4*)den, denN4);
    gemm_kernel<0><<<gemm_grid, 256>>>(x, W1, nullptr, h1, N, DFEAT, 128);
    alpha_kernel<<<alpha_blocks, 256>>>(h1, a_src1, a_dst1, as, ad, N);
    edge_w_kernel<<<edgew_blocks, 256>>>(ei, as, ad, wb, den, E, Etot);
    edge_agg_kernel<<<agg_blocks, 256>>>(ei, h1, wb, den, agg1, E, Etot);

    // ---- layer 2 (input = relu(agg1 + b1), fused into GEMM A-load) ----
    zero_kernel<<<(featN4 + 255) / 256, 256>>>((float4*)agg2, featN4);
    zero_kernel<<<(denN4 + 255) / 256, 256>>>((float4*)den, denN4);
    gemm_kernel<1><<<gemm_grid, 256>>>(agg1, W2, b1, h2, N, DFEAT, DFEAT);
    alpha_kernel<<<alpha_blocks, 256>>>(h2, a_src2, a_dst2, as, ad, N);
    edge_w_kernel<<<edgew_blocks, 256>>>(ei, as, ad, wb, den, E, Etot);
    edge_agg_kernel<<<agg_blocks, 256>>>(ei, h2, wb, den, agg2, E, Etot);

    // ---- collapsed post-MLP + sigmoid ----
    wc_kernel<<<1, 256>>>(Wp1, bp1, Wp2, bp2, wc);
    final_kernel<<<final_blocks, 256>>>(agg2, b2, wc, (float*)d_out, N);
}

// round 3
// speedup vs baseline: 3.1609x; 3.1609x over previous
#include <cuda_runtime.h>
#include <math.h>
#include <stdint.h>

#define NNODES 50000
#define EEDGES 800000
#define ETOT   (EEDGES + NNODES)
#define DHID   128
#define DFEAT  256          // HEADS * HID
#define NEG_SLOPE 0.2f
#define EPSV 1e-16f
#define NB_SCAN ((NNODES + 255) / 256)

// ---------------- scratch (no allocation allowed) ----------------
__device__ float g_h1[NNODES * DFEAT];
__device__ float g_agg1[NNODES * DFEAT];
__device__ float g_h2[NNODES * DFEAT];
__device__ float g_agg2[NNODES * DFEAT];
__device__ float g_as[NNODES * 2];
__device__ float g_ad[NNODES * 2];
__device__ float g_wc[DFEAT + 1];
__device__ int   g_cnt[NNODES];
__device__ int   g_rowptr[NNODES];
__device__ int   g_cursor[NNODES];
__device__ int   g_colidx[ETOT];
__device__ int   g_bsum[256];

// ================= CSR construction =================
__global__ void zero_int_kernel(int* p, int n) {
    int i = blockIdx.x * blockDim.x + threadIdx.x;
    if (i < n) p[i] = 0;
}

__global__ void count_kernel(const int* __restrict__ ei, int* __restrict__ cnt,
                             int E, int Etot) {
    int t = blockIdx.x * blockDim.x + threadIdx.x;
    if (t >= Etot) return;
    int d = (t < E) ? ei[E + t] : (t - E);
    atomicAdd(&cnt[d], 1);
}

__global__ void scan_block_sums(const int* __restrict__ cnt, int* __restrict__ bsum, int N) {
    __shared__ int sh[256];
    int tid = threadIdx.x;
    int i = blockIdx.x * 256 + tid;
    sh[tid] = (i < N) ? cnt[i] : 0;
    __syncthreads();
    for (int s = 128; s > 0; s >>= 1) {
        if (tid < s) sh[tid] += sh[tid + s];
        __syncthreads();
    }
    if (tid == 0) bsum[blockIdx.x] = sh[0];
}

__global__ void scan_bsums(int* bsum, int nb) {
    __shared__ int sh[256];
    int tid = threadIdx.x;
    int v0 = (tid < nb) ? bsum[tid] : 0;
    sh[tid] = v0;
    __syncthreads();
    for (int off = 1; off < 256; off <<= 1) {
        int v = (tid >= off) ? sh[tid - off] : 0;
        __syncthreads();
        sh[tid] += v;
        __syncthreads();
    }
    if (tid < nb) bsum[tid] = sh[tid] - v0;   // exclusive
}

__global__ void scan_final(const int* __restrict__ cnt, const int* __restrict__ bsum,
                           int* __restrict__ rowptr, int* __restrict__ cursor, int N) {
    __shared__ int sh[256];
    int tid = threadIdx.x;
    int i = blockIdx.x * 256 + tid;
    int v0 = (i < N) ? cnt[i] : 0;
    sh[tid] = v0;
    __syncthreads();
    for (int off = 1; off < 256; off <<= 1) {
        int v = (tid >= off) ? sh[tid - off] : 0;
        __syncthreads();
        sh[tid] += v;
        __syncthreads();
    }
    if (i < N) {
        int excl = sh[tid] - v0 + bsum[blockIdx.x];
        rowptr[i] = excl;
        cursor[i] = excl;
    }
}

__global__ void scatter_kernel(const int* __restrict__ ei, int* __restrict__ cursor,
                               int* __restrict__ colidx, int E, int Etot) {
    int t = blockIdx.x * blockDim.x + threadIdx.x;
    if (t >= Etot) return;
    int s, d;
    if (t < E) { s = ei[t]; d = ei[E + t]; } else { s = d = t - E; }
    int pos = atomicAdd(&cursor[d], 1);
    colidx[pos] = s;
}

// ================= 3xTF32 tensor-core GEMM =================
// C[M,N] = op(A)[M,K] @ B[K,N];  op(A) = relu(A + bias[k]) if FUSE_RELU.
// BM=128, BN=64, BK=16, 256 threads, warp grid 4(m) x 2(n), warp tile 32x32.
__device__ __forceinline__ uint32_t f2tf32(float f) {
    uint32_t u;
    asm("cvt.rna.tf32.f32 %0, %1;" : "=r"(u) : "f"(f));
    return u;
}

__device__ __forceinline__ void mma_tf32(float* c, const uint32_t* a, const uint32_t* b) {
    asm volatile(
        "mma.sync.aligned.m16n8k8.row.col.f32.tf32.tf32.f32 "
        "{%0,%1,%2,%3}, {%4,%5,%6,%7}, {%8,%9}, {%0,%1,%2,%3};"
        : "+f"(c[0]), "+f"(c[1]), "+f"(c[2]), "+f"(c[3])
        : "r"(a[0]), "r"(a[1]), "r"(a[2]), "r"(a[3]), "r"(b[0]), "r"(b[1]));
}

template <int FUSE_RELU>
__global__ void __launch_bounds__(256) gemm_tf32_kernel(
    const float* __restrict__ A, const float* __restrict__ B,
    const float* __restrict__ bias, float* __restrict__ C,
    int M, int N, int K)
{
    __shared__ uint32_t Ah[128][20];   // pad 4: frag bank = 4*gid+tig (bijective)
    __shared__ uint32_t Al[128][20];
    __shared__ uint32_t Bh[16][72];    // pad 8: frag bank = 8*tig+gid (bijective)
    __shared__ uint32_t Bl[16][72];

    const int tid  = threadIdx.x;
    const int lane = tid & 31;
    const int warp = tid >> 5;
    const int wm   = warp & 3;     // m warp: wm*32
    const int wn   = warp >> 2;    // n warp: wn*32
    const int gid  = lane >> 2;
    const int tig  = lane & 3;
    const int m0 = blockIdx.x * 128;
    const int n0 = blockIdx.y * 64;

    float c[2][4][4];
#pragma unroll
    for (int fm = 0; fm < 2; fm++)
#pragma unroll
        for (int fn = 0; fn < 4; fn++)
#pragma unroll
            for (int j = 0; j < 4; j++) c[fm][fn][j] = 0.f;

    for (int k0 = 0; k0 < K; k0 += 16) {
        // ---- load A tile (128x16): 512 float4, 2 per thread ----
#pragma unroll
        for (int it = 0; it < 2; it++) {
            int idx = tid + it * 256;
            int row = idx >> 2, c4 = idx & 3;
            int gm = m0 + row;
            float4 f = make_float4(0.f, 0.f, 0.f, 0.f);
            if (gm < M) f = *(const float4*)&A[(size_t)gm * K + k0 + c4 * 4];
            if (FUSE_RELU) {
                float4 bb = *(const float4*)&bias[k0 + c4 * 4];
                f.x = fmaxf(f.x + bb.x, 0.f);
                f.y = fmaxf(f.y + bb.y, 0.f);
                f.z = fmaxf(f.z + bb.z, 0.f);
                f.w = fmaxf(f.w + bb.w, 0.f);
            }
            uint32_t h0 = f2tf32(f.x), h1 = f2tf32(f.y), h2 = f2tf32(f.z), h3 = f2tf32(f.w);
            uint32_t l0 = f2tf32(f.x - __uint_as_float(h0));
            uint32_t l1 = f2tf32(f.y - __uint_as_float(h1));
            uint32_t l2 = f2tf32(f.z - __uint_as_float(h2));
            uint32_t l3 = f2tf32(f.w - __uint_as_float(h3));
            *(uint4*)&Ah[row][c4 * 4] = make_uint4(h0, h1, h2, h3);
            *(uint4*)&Al[row][c4 * 4] = make_uint4(l0, l1, l2, l3);
        }
        // ---- load B tile (16x64): 256 float4, 1 per thread ----
        {
            int row = tid >> 4, c4 = tid & 15;
            float4 f = *(const float4*)&B[(size_t)(k0 + row) * N + n0 + c4 * 4];
            uint32_t h0 = f2tf32(f.x), h1 = f2tf32(f.y), h2 = f2tf32(f.z), h3 = f2tf32(f.w);
            uint32_t l0 = f2tf32(f.x - __uint_as_float(h0));
            uint32_t l1 = f2tf32(f.y - __uint_as_float(h1));
            uint32_t l2 = f2tf32(f.z - __uint_as_float(h2));
            uint32_t l3 = f2tf32(f.w - __uint_as_float(h3));
            *(uint4*)&Bh[row][c4 * 4] = make_uint4(h0, h1, h2, h3);
            *(uint4*)&Bl[row][c4 * 4] = make_uint4(l0, l1, l2, l3);
        }
        __syncthreads();

#pragma unroll
        for (int kk = 0; kk < 2; kk++) {
            uint32_t ah[2][4], al[2][4], bh[4][2], bl[4][2];
#pragma unroll
            for (int fm = 0; fm < 2; fm++) {
                int r = wm * 32 + fm * 16;
                int cA = kk * 8 + tig;
                ah[fm][0] = Ah[r + gid][cA];         al[fm][0] = Al[r + gid][cA];
                ah[fm][1] = Ah[r + gid + 8][cA];     al[fm][1] = Al[r + gid + 8][cA];
                ah[fm][2] = Ah[r + gid][cA + 4];     al[fm][2] = Al[r + gid][cA + 4];
                ah[fm][3] = Ah[r + gid + 8][cA + 4]; al[fm][3] = Al[r + gid + 8][cA + 4];
            }
#pragma unroll
            for (int fn = 0; fn < 4; fn++) {
                int cc = wn * 32 + fn * 8 + gid;
                bh[fn][0] = Bh[kk * 8 + tig][cc];     bl[fn][0] = Bl[kk * 8 + tig][cc];
                bh[fn][1] = Bh[kk * 8 + tig + 4][cc]; bl[fn][1] = Bl[kk * 8 + tig + 4][cc];
            }
#pragma unroll
            for (int fm = 0; fm < 2; fm++)
#pragma unroll
                for (int fn = 0; fn < 4; fn++) {
                    mma_tf32(c[fm][fn], ah[fm], bh[fn]);   // hi*hi
                    mma_tf32(c[fm][fn], ah[fm], bl[fn]);   // hi*lo
                    mma_tf32(c[fm][fn], al[fm], bh[fn]);   // lo*hi
                }
        }
        __syncthreads();
    }

    // ---- epilogue ----
#pragma unroll
    for (int fm = 0; fm < 2; fm++)
#pragma unroll
        for (int fn = 0; fn < 4; fn++) {
            int gm = m0 + wm * 32 + fm * 16 + gid;
            int gn = n0 + wn * 32 + fn * 8 + 2 * tig;
            if (gm < M)
                *(float2*)&C[(size_t)gm * N + gn] = make_float2(c[fm][fn][0], c[fm][fn][1]);
            if (gm + 8 < M)
                *(float2*)&C[(size_t)(gm + 8) * N + gn] = make_float2(c[fm][fn][2], c[fm][fn][3]);
        }
}

// ================= attention logits =================
__global__ void alpha_kernel(const float* __restrict__ h,
                             const float* __restrict__ a_src,
                             const float* __restrict__ a_dst,
                             float* __restrict__ as_out, float* __restrict__ ad_out,
                             int N)
{
    int gw = (blockIdx.x * blockDim.x + threadIdx.x) >> 5;
    int lane = threadIdx.x & 31;
    if (gw >= N * 2) return;
    int n = gw >> 1, hh = gw & 1;
    const float* hp = h + (size_t)n * DFEAT + hh * DHID;
    float4 v = *(const float4*)&hp[lane * 4];
    float4 s = *(const float4*)&a_src[hh * DHID + lane * 4];
    float4 d = *(const float4*)&a_dst[hh * DHID + lane * 4];
    float accs = v.x * s.x + v.y * s.y + v.z * s.z + v.w * s.w;
    float accd = v.x * d.x + v.y * d.y + v.z * d.z + v.w * d.w;
#pragma unroll
    for (int o = 16; o; o >>= 1) {
        accs += __shfl_xor_sync(0xffffffffu, accs, o);
        accd += __shfl_xor_sync(0xffffffffu, accd, o);
    }
    if (lane == 0) { as_out[gw] = accs; ad_out[gw] = accd; }
}

// ================= fused CSR softmax-aggregation =================
// One warp per dst node, both heads; atomic-free single pass.
__global__ void agg_csr_kernel(const int* __restrict__ rowptr, const int* __restrict__ cnt,
                               const int* __restrict__ colidx,
                               const float* __restrict__ h,
                               const float* __restrict__ as_in, const float* __restrict__ ad_in,
                               float* __restrict__ out, int N)
{
    int gw = (blockIdx.x * blockDim.x + threadIdx.x) >> 5;
    int lane = threadIdx.x & 31;
    if (gw >= N) return;
    int start = rowptr[gw];
    int deg   = cnt[gw];
    float2 adv = ((const float2*)ad_in)[gw];
    const float4* h4 = (const float4*)h;

    float4 acc0 = make_float4(0.f, 0.f, 0.f, 0.f);
    float4 acc1 = make_float4(0.f, 0.f, 0.f, 0.f);
    float den0 = 0.f, den1 = 0.f;

    for (int i = start; i < start + deg; i++) {
        int s = __ldg(&colidx[i]);
        float2 av = ((const float2*)as_in)[s];
        float e0 = av.x + adv.x;  e0 = e0 > 0.f ? e0 : NEG_SLOPE * e0;
        float e1 = av.y + adv.y;  e1 = e1 > 0.f ? e1 : NEG_SLOPE * e1;
        float w0 = __expf(e0);
        float w1 = __expf(e1);
        den0 += w0;  den1 += w1;
        float4 v0 = h4[(size_t)s * 64 + lane];
        float4 v1 = h4[(size_t)s * 64 + 32 + lane];
        acc0.x = fmaf(w0, v0.x, acc0.x); acc0.y = fmaf(w0, v0.y, acc0.y);
        acc0.z = fmaf(w0, v0.z, acc0.z); acc0.w = fmaf(w0, v0.w, acc0.w);
        acc1.x = fmaf(w1, v1.x, acc1.x); acc1.y = fmaf(w1, v1.y, acc1.y);
        acc1.z = fmaf(w1, v1.z, acc1.z); acc1.w = fmaf(w1, v1.w, acc1.w);
    }
    float r0 = 1.f / (den0 + EPSV);
    float r1 = 1.f / (den1 + EPSV);
    ((float4*)out)[(size_t)gw * 64 + lane] =
        make_float4(acc0.x * r0, acc0.y * r0, acc0.z * r0, acc0.w * r0);
    ((float4*)out)[(size_t)gw * 64 + 32 + lane] =
        make_float4(acc1.x * r1, acc1.y * r1, acc1.z * r1, acc1.w * r1);
}

// ================= collapsed post-MLP =================
__global__ void wc_kernel(const float* __restrict__ Wp1, const float* __restrict__ bp1,
                          const float* __restrict__ Wp2, const float* __restrict__ bp2,
                          float* __restrict__ wc)
{
    int i = threadIdx.x;  // 256 threads
    float acc = 0.f;
    for (int j = 0; j < DHID; j++) acc += Wp1[i * DHID + j] * Wp2[j];
    wc[i] = acc;
    if (i == 0) {
        float b = 0.f;
        for (int j = 0; j < DHID; j++) b += bp1[j] * Wp2[j];
        wc[DFEAT] = b + bp2[0];
    }
}

__global__ void final_kernel(const float* __restrict__ agg2,
                             const float* __restrict__ b2,
                             const float* __restrict__ wc,
                             float* __restrict__ out, int N)
{
    int gw = (blockIdx.x * blockDim.x + threadIdx.x) >> 5;
    int lane = threadIdx.x & 31;
    if (gw >= N) return;
    const float* hp = agg2 + (size_t)gw * DFEAT;
    float acc = 0.f;
#pragma unroll
    for (int r = 0; r < 2; r++) {
        int cidx = r * 128 + lane * 4;
        float4 v  = *(const float4*)&hp[cidx];
        float4 bb = *(const float4*)&b2[cidx];
        float4 ww = *(const float4*)&wc[cidx];
        acc += fmaxf(v.x + bb.x, 0.f) * ww.x;
        acc += fmaxf(v.y + bb.y, 0.f) * ww.y;
        acc += fmaxf(v.z + bb.z, 0.f) * ww.z;
        acc += fmaxf(v.w + bb.w, 0.f) * ww.w;
    }
#pragma unroll
    for (int o = 16; o; o >>= 1) acc += __shfl_xor_sync(0xffffffffu, acc, o);
    if (lane == 0) {
        float z = acc + wc[DFEAT];
        out[gw] = 1.f / (1.f + expf(-z));
    }
}

// ================= launch =================
extern "C" void kernel_launch(void* const* d_in, const int* in_sizes, int n_in,
                              void* d_out, int out_size)
{
    const float* x      = (const float*)d_in[0];
    const int*   ei     = (const int*)  d_in[1];
    const float* W1     = (const float*)d_in[2];
    const float* a_src1 = (const float*)d_in[3];
    const float* a_dst1 = (const float*)d_in[4];
    const float* b1     = (const float*)d_in[5];
    const float* W2     = (const float*)d_in[6];
    const float* a_src2 = (const float*)d_in[7];
    const float* a_dst2 = (const float*)d_in[8];
    const float* b2     = (const float*)d_in[9];
    const float* Wp1    = (const float*)d_in[10];
    const float* bp1    = (const float*)d_in[11];
    const float* Wp2    = (const float*)d_in[12];
    const float* bp2    = (const float*)d_in[13];

    const int N = in_sizes[0] / 128;
    const int E = in_sizes[1] / 2;
    const int Etot = E + N;

    float *h1, *agg1, *h2, *agg2, *as, *ad, *wc;
    int *cnt, *rowptr, *cursor, *colidx, *bsum;
    cudaGetSymbolAddress((void**)&h1,   g_h1);
    cudaGetSymbolAddress((void**)&agg1, g_agg1);
    cudaGetSymbolAddress((void**)&h2,   g_h2);
    cudaGetSymbolAddress((void**)&agg2, g_agg2);
    cudaGetSymbolAddress((void**)&as,   g_as);
    cudaGetSymbolAddress((void**)&ad,   g_ad);
    cudaGetSymbolAddress((void**)&wc,   g_wc);
    cudaGetSymbolAddress((void**)&cnt,    g_cnt);
    cudaGetSymbolAddress((void**)&rowptr, g_rowptr);
    cudaGetSymbolAddress((void**)&cursor, g_cursor);
    cudaGetSymbolAddress((void**)&colidx, g_colidx);
    cudaGetSymbolAddress((void**)&bsum,   g_bsum);

    const int nb = (N + 255) / 256;
    dim3 gemm_grid((N + 127) / 128, DFEAT / 64);
    const int alpha_blocks = (N * 2 * 32 + 255) / 256;
    const int agg_blocks   = (N * 32 + 255) / 256;
    const int final_blocks = (N * 32 + 255) / 256;
    const int edge_blocks  = (Etot + 255) / 256;

    // ---- CSR build (shared by both layers) ----
    zero_int_kernel<<<nb, 256>>>(cnt, N);
    count_kernel<<<edge_blocks, 256>>>(ei, cnt, E, Etot);
    scan_block_sums<<<nb, 256>>>(cnt, bsum, N);
    scan_bsums<<<1, 256>>>(bsum, nb);
    scan_final<<<nb, 256>>>(cnt, bsum, rowptr, cursor, N);
    scatter_kernel<<<edge_blocks, 256>>>(ei, cursor, colidx, E, Etot);

    // ---- layer 1 ----
    gemm_tf32_kernel<0><<<gemm_grid, 256>>>(x, W1, nullptr, h1, N, DFEAT, 128);
    alpha_kernel<<<alpha_blocks, 256>>>(h1, a_src1, a_dst1, as, ad, N);
    agg_csr_kernel<<<agg_blocks, 256>>>(rowptr, cnt, colidx, h1, as, ad, agg1, N);

    // ---- layer 2 (input = relu(agg1 + b1), fused into GEMM A-load) ----
    gemm_tf32_kernel<1><<<gemm_grid, 256>>>(agg1, W2, b1, h2, N, DFEAT, DFEAT);
    alpha_kernel<<<alpha_blocks, 256>>>(h2, a_src2, a_dst2, as, ad, N);
    agg_csr_kernel<<<agg_blocks, 256>>>(rowptr, cnt, colidx, h2, as, ad, agg2, N);

    // ---- collapsed post-MLP + sigmoid ----
    wc_kernel<<<1, 256>>>(Wp1, bp1, Wp2, bp2, wc);
    final_kernel<<<final_blocks, 256>>>(agg2, b2, wc, (float*)d_out, N);
}